// round 4
// baseline (speedup 1.0000x reference)
#include <cuda_runtime.h>

#define BB 4
#define NN 4096
#define MM 4096
#define DD 128
#define KK 64
#define GC 20
#define NCELL (GC*GC)
#define TIE_CAP 96
#define NBLK 128
#define NTHR 1024
#define FULLM 0xffffffffu
#define TK_WARPS 4
#define WCAP 1024
#define TAU 0.012f
#define TSC (256.0f/TAU)

// scratch (static device globals — zero-initialized at module load)
__device__ int    g_cellCnt[BB*NCELL];
__device__ int    g_cellStart[BB*(NCELL+1)];
__device__ int    g_cursor[BB*NCELL];
__device__ float2 g_slocs[BB*NN];
__device__ int    g_sid[BB*NN];
__device__ int    g_idx[BB*MM*KK];
__device__ float  g_p[BB*MM*KK];
__device__ int    g_tcnt[BB*NN];
__device__ int    g_toff[BB*(NN+1)];
__device__ int    g_tcur[BB*NN];
__device__ int2   g_tre[BB*MM*KK];     // (row_in_batch, p bits)
__device__ float  g_eu[BB*MM];
__device__ float  g_evt[BB*NN];
__device__ unsigned g_barcnt;
__device__ unsigned g_bargen;

__global__ void k_count(const float2* __restrict__ slocs) {
    int i = blockIdx.x*256 + threadIdx.x;
    if (i >= BB*NN) return;
    float2 p = slocs[i];
    int b = i / NN;
    int cx = min(GC-1, max(0, (int)(p.x * GC)));
    int cy = min(GC-1, max(0, (int)(p.y * GC)));
    atomicAdd(&g_cellCnt[b*NCELL + cy*GC + cx], 1);
}

__global__ void k_scan() {
    __shared__ int sc[512];
    int b = blockIdx.x, t = threadIdx.x;
    int v = (t < NCELL) ? g_cellCnt[b*NCELL + t] : 0;
    sc[t] = v;
    __syncthreads();
    for (int off = 1; off < 512; off <<= 1) {
        int x = (t >= off) ? sc[t-off] : 0;
        __syncthreads();
        sc[t] += x;
        __syncthreads();
    }
    if (t < NCELL) {
        int excl = sc[t] - v;
        g_cellStart[b*(NCELL+1) + t] = excl;
        g_cursor[b*NCELL + t] = excl;
        g_cellCnt[b*NCELL + t] = 0;          // self-clean for next replay
    }
    if (t == NCELL-1) g_cellStart[b*(NCELL+1) + NCELL] = sc[t];
}

__global__ void k_fill(const float2* __restrict__ slocs) {
    int i = blockIdx.x*256 + threadIdx.x;
    if (i >= BB*NN) return;
    float2 p = slocs[i];
    int b = i / NN, n = i - b*NN;
    int cx = min(GC-1, max(0, (int)(p.x * GC)));
    int cy = min(GC-1, max(0, (int)(p.y * GC)));
    int pos = atomicAdd(&g_cursor[b*NCELL + cy*GC + cx], 1);
    g_slocs[b*NN + pos] = p;
    g_sid[b*NN + pos] = n;
}

// ---------------------------------------------------------------------------
// top-k: warp per row. Single traversal into smem buffer + tau-restricted
// fine histogram (atomics cut ~3x). Selection + emit entirely from buffer.
// Also accumulates transpose column counts (g_tcnt).
// ---------------------------------------------------------------------------
__global__ void __launch_bounds__(TK_WARPS*32) k_topk(const float2* __restrict__ tlocs) {
    __shared__ float          s_cd[TK_WARPS][WCAP];
    __shared__ unsigned short s_cj[TK_WARPS][WCAP];
    __shared__ int            s_hist[TK_WARPS][256];
    __shared__ float          s_td[TK_WARPS][TIE_CAP];
    __shared__ unsigned short s_tj[TK_WARPS][TIE_CAP];

    int warp = threadIdx.x >> 5, lane = threadIdx.x & 31;
    int row = blockIdx.x*TK_WARPS + warp;
    int b = row >> 12;
    unsigned lmask = (1u << lane) - 1u;

    float2 t = tlocs[row];
    int cx = min(GC-1, max(0, (int)(t.x*GC)));
    int cy = min(GC-1, max(0, (int)(t.y*GC)));
    int x0 = max(cx-3, 0), x1 = min(cx+3, GC-1);
    int y0 = max(cy-3, 0), y1 = min(cy+3, GC-1);
    const int* cs = &g_cellStart[b*(NCELL+1)];
    const float2* sl = &g_slocs[b*NN];
    const int* sid = &g_sid[b*NN];
    int* tc = &g_tcnt[b*NN];

    #pragma unroll
    for (int i = 0; i < 8; i++) s_hist[warp][lane*8+i] = 0;
    __syncwarp();

    int cnt = 0, ctau = 0, ncov = 0;
    // pass over grid box
    for (int yy = y0; yy <= y1; yy++) {
        int lo = cs[yy*GC + x0];
        int hi = cs[yy*GC + x1 + 1];
        for (int base = lo; base < hi; base += 32) {
            int j = base + lane;
            float d = 1e9f;
            if (j < hi) {
                float2 s = sl[j];
                float dx = t.x - s.x, dy = t.y - s.y;
                d = fmaf(dy, dy, dx*dx);
            }
            bool hit = d < 0.04f;
            unsigned bm = __ballot_sync(FULLM, hit);
            int p = cnt + __popc(bm & lmask);
            if (hit && p < WCAP) { s_cd[warp][p] = d; s_cj[warp][p] = (unsigned short)j; }
            cnt += __popc(bm);
            bool ht = d < TAU;
            if (ht) atomicAdd(&s_hist[warp][min(255,(int)(d*TSC))], 1);
            ctau += __popc(__ballot_sync(FULLM, ht));
            ncov += __popc(__ballot_sync(FULLM, d < 0.0225f));
        }
    }
    if (ncov < KK) {
        // rare: box coverage insufficient -> rescan all sources
        #pragma unroll
        for (int i = 0; i < 8; i++) s_hist[warp][lane*8+i] = 0;
        __syncwarp();
        cnt = 0; ctau = 0;
        for (int base = 0; base < NN; base += 32) {
            int j = base + lane;
            float2 s = sl[j];
            float dx = t.x - s.x, dy = t.y - s.y;
            float d = fmaf(dy, dy, dx*dx);
            bool hit = d < 0.04f;
            unsigned bm = __ballot_sync(FULLM, hit);
            int p = cnt + __popc(bm & lmask);
            if (hit && p < WCAP) { s_cd[warp][p] = d; s_cj[warp][p] = (unsigned short)j; }
            cnt += __popc(bm);
            bool ht = d < TAU;
            if (ht) atomicAdd(&s_hist[warp][min(255,(int)(d*TSC))], 1);
            ctau += __popc(__ballot_sync(FULLM, ht));
        }
    }
    __syncwarp();
    cnt = min(cnt, WCAP);

    const float kInv = 99.9999f;   // 1/(EPSILON+1e-8)
    int*   oid = &g_idx[(size_t)row*KK];
    float* op  = &g_p[(size_t)row*KK];

    if (cnt <= KK) {
        for (int p = lane; p < KK; p += 32) {
            if (p < cnt) {
                int s = sid[s_cj[warp][p]];
                oid[p] = s; op[p] = __expf(-s_cd[warp][p]*kInv);
                atomicAdd(&tc[s], 1);
            } else { oid[p] = 0; op[p] = 0.0f; }
        }
        return;
    }

    float hsc, hbound;
    if (ctau >= KK) { hsc = TSC; hbound = TAU; }
    else {
        // boundary row: rebuild coarse hist from buffer (smem only)
        #pragma unroll
        for (int i = 0; i < 8; i++) s_hist[warp][lane*8+i] = 0;
        __syncwarp();
        for (int ii = lane; ii < cnt; ii += 32)
            atomicAdd(&s_hist[warp][min(255,(int)(s_cd[warp][ii]*6400.0f))], 1);
        __syncwarp();
        hsc = 6400.0f; hbound = 0.04f;
    }

    // threshold bin via warp prefix over 256 bins
    int h[8]; int part = 0;
    #pragma unroll
    for (int i = 0; i < 8; i++) { h[i] = s_hist[warp][lane*8+i]; part += h[i]; }
    int inc = part;
    #pragma unroll
    for (int off = 1; off < 32; off <<= 1) {
        int y = __shfl_up_sync(FULLM, inc, off);
        if (lane >= off) inc += y;
    }
    int exc = inc - part;
    int tb = -1, r = 0;
    if (exc < KK && KK <= inc) {
        int c = exc;
        #pragma unroll
        for (int i = 0; i < 8; i++) {
            if (tb < 0) {
                if (c + h[i] >= KK) { tb = lane*8 + i; r = KK - c; }
                else c += h[i];
            }
        }
    }
    int srcl = __ffs(__ballot_sync(FULLM, tb >= 0)) - 1;
    tb = __shfl_sync(FULLM, tb, srcl);
    r  = __shfl_sync(FULLM, r,  srcl);

    // emit from buffer
    int pos = 0, ntie = 0;
    for (int base = 0; base < cnt; base += 32) {
        int ii = base + lane;
        bool v = ii < cnt;
        float d = v ? s_cd[warp][ii] : 1e9f;
        int   j = v ? s_cj[warp][ii] : 0;
        int bn = (d < hbound) ? min(255,(int)(d*hsc)) : 300;
        bool sel = bn < tb, tie = bn == tb;
        unsigned bs = __ballot_sync(FULLM, sel);
        int p = pos + __popc(bs & lmask);
        if (sel) {
            int s = sid[j];
            oid[p] = s; op[p] = __expf(-d*kInv);
            atomicAdd(&tc[s], 1);
        }
        pos += __popc(bs);
        unsigned bt = __ballot_sync(FULLM, tie);
        int q = ntie + __popc(bt & lmask);
        if (tie && q < TIE_CAP) { s_td[warp][q] = d; s_tj[warp][q] = (unsigned short)j; }
        ntie += __popc(bt);
    }
    __syncwarp();
    if (lane == 0) {
        int nt = min(ntie, TIE_CAP);
        int rr = min(r, nt);
        for (int k2 = 0; k2 < rr; k2++) {
            float best = 1e30f; int bj = 0;
            for (int j2 = 0; j2 < nt; j2++)
                if (s_td[warp][j2] < best) { best = s_td[warp][j2]; bj = j2; }
            int s = sid[s_tj[warp][bj]];
            oid[pos+k2] = s; op[pos+k2] = __expf(-best*kInv);
            atomicAdd(&tc[s], 1);
            s_td[warp][bj] = 1e30f;
        }
        for (int k2 = rr; k2 < r; k2++) { oid[pos+k2] = 0; op[pos+k2] = 0.0f; }
    }
}

// ---- transpose CSR build ----
__global__ void k_tscan() {      // grid BB x 1024
    __shared__ int sp[1024];
    int b = blockIdx.x, t = threadIdx.x;
    int base = b*NN + t*4;
    int c0 = g_tcnt[base], c1 = g_tcnt[base+1], c2 = g_tcnt[base+2], c3 = g_tcnt[base+3];
    g_tcnt[base] = 0; g_tcnt[base+1] = 0; g_tcnt[base+2] = 0; g_tcnt[base+3] = 0;  // self-clean
    int tot = c0+c1+c2+c3;
    sp[t] = tot;
    __syncthreads();
    for (int off = 1; off < 1024; off <<= 1) {
        int v = (t >= off) ? sp[t-off] : 0;
        __syncthreads();
        sp[t] += v;
        __syncthreads();
    }
    int o = b*MM*KK + (sp[t] - tot);
    int* off = &g_toff[b*(NN+1)];
    int* cur = &g_tcur[b*NN];
    off[t*4+0] = o;            cur[t*4+0] = o;
    off[t*4+1] = o+c0;         cur[t*4+1] = o+c0;
    off[t*4+2] = o+c0+c1;      cur[t*4+2] = o+c0+c1;
    off[t*4+3] = o+c0+c1+c2;   cur[t*4+3] = o+c0+c1+c2;
    if (t == 1023) off[NN] = o + tot;
}

__global__ void k_tfill() {      // grid 4096 x 256
    int i = blockIdx.x*256 + threadIdx.x;
    float p = g_p[i];
    if (p == 0.0f) return;
    int r = i >> 6;
    int b = r >> 12;
    int c = g_idx[i];
    int pos = atomicAdd(&g_tcur[b*NN + c], 1);
    g_tre[pos] = make_int2(r & (MM-1), __float_as_int(p));
}

// ---------------------------------------------------------------------------
// persistent Sinkhorn (atomic-free: transpose-CSR v-phase, smem-staged
// tables) + fused output GEMM.
// ---------------------------------------------------------------------------
__device__ __forceinline__ unsigned ld_acq(const unsigned* p) {
    unsigned v;
    asm volatile("ld.acquire.gpu.u32 %0, [%1];" : "=r"(v) : "l"(p) : "memory");
    return v;
}
__device__ __forceinline__ void st_rel(unsigned* p, unsigned v) {
    asm volatile("st.release.gpu.u32 [%0], %1;" :: "l"(p), "r"(v) : "memory");
}
__device__ __forceinline__ void gridbar() {
    __syncthreads();
    if (threadIdx.x == 0) {
        unsigned g = ld_acq(&g_bargen);
        __threadfence();
        if (atomicAdd(&g_barcnt, 1u) == NBLK - 1) {
            g_barcnt = 0;
            st_rel(&g_bargen, g + 1);
        } else {
            while (ld_acq(&g_bargen) == g) { __nanosleep(20); }
        }
    }
    __syncthreads();
}

__global__ void __launch_bounds__(NTHR, 1) k_sink(const float* __restrict__ feats,
                                                  float* __restrict__ out) {
    __shared__ float s_tab[NN];
    int lane = threadIdx.x & 31;
    int warp = threadIdx.x >> 5;       // 0..31
    int blk = blockIdx.x;              // 0..127
    int b = blk >> 5;                  // 32 blocks per batch
    int bofs = b * NN;

    int   i0[4], i1[4];
    float p0[4], p1[4], eu[4];
    int   clo[4], chi[4];
    int rbase = blk*128 + warp*4;      // global row base (batch-aligned)
    int cbase = (blk & 31)*128 + warp*4;  // column base within batch

    #pragma unroll
    for (int k = 0; k < 4; k++) {
        int r = rbase + k;
        const int*   ri = &g_idx[(size_t)r*KK];
        const float* rp = &g_p[(size_t)r*KK];
        i0[k] = ri[lane];   i1[k] = ri[lane+32];
        p0[k] = rp[lane];   p1[k] = rp[lane+32];
        clo[k] = g_toff[b*(NN+1) + cbase + k];
        chi[k] = g_toff[b*(NN+1) + cbase + k + 1];
    }

    #pragma unroll 1
    for (int t = 0; t < 8; t++) {
        // ---- phase A: eu per row ----
        if (t > 0) {
            #pragma unroll
            for (int x = 0; x < NN/NTHR; x++)
                s_tab[threadIdx.x + x*NTHR] = __ldcg(&g_evt[bofs + threadIdx.x + x*NTHR]);
        }
        __syncthreads();
        #pragma unroll
        for (int k = 0; k < 4; k++) {
            float s;
            if (t == 0) s = p0[k] + p1[k];              // ev == 1 initially
            else        s = p0[k]*s_tab[i0[k]] + p1[k]*s_tab[i1[k]];
            #pragma unroll
            for (int o = 16; o; o >>= 1) s += __shfl_xor_sync(FULLM, s, o);
            eu[k] = (s > 0.0f) ? 1.0f/s : 0.0f;
            if (lane == 0) g_eu[rbase + k] = eu[k];
        }
        gridbar();
        // ---- phase B: ev per column via transpose CSR ----
        #pragma unroll
        for (int x = 0; x < NN/NTHR; x++)
            s_tab[threadIdx.x + x*NTHR] = __ldcg(&g_eu[b*MM + threadIdx.x + x*NTHR]);
        __syncthreads();
        #pragma unroll
        for (int k = 0; k < 4; k++) {
            float s = 0.0f;
            for (int q = clo[k] + lane; q < chi[k]; q += 32) {
                int2 e = g_tre[q];
                s += __int_as_float(e.y) * s_tab[e.x];
            }
            #pragma unroll
            for (int o = 16; o; o >>= 1) s += __shfl_xor_sync(FULLM, s, o);
            if (lane == 0) g_evt[bofs + cbase + k] = (s > 0.0f) ? 1.0f/s : 0.0f;
        }
        gridbar();
    }

    // ---- epilogue: out[r,:] = sum_j p_j*eu_r*ev_{i_j} * feats[i_j,:] ----
    #pragma unroll
    for (int x = 0; x < NN/NTHR; x++)
        s_tab[threadIdx.x + x*NTHR] = __ldcg(&g_evt[bofs + threadIdx.x + x*NTHR]);
    __syncthreads();
    const float* fb = feats + (size_t)b*NN*DD;
    #pragma unroll 1
    for (int k = 0; k < 4; k++) {
        int r = rbase + k;
        float w0 = p0[k]*eu[k]*s_tab[i0[k]];
        float w1 = p1[k]*eu[k]*s_tab[i1[k]];
        float4 acc = make_float4(0.f, 0.f, 0.f, 0.f);
        #pragma unroll 16
        for (int j = 0; j < KK; j++) {
            int src = j & 31;
            float wj = __shfl_sync(FULLM, (j < 32) ? w0 : w1, src);
            int   ij = __shfl_sync(FULLM, (j < 32) ? i0[k] : i1[k], src);
            const float4* f4 = (const float4*)(fb + (size_t)ij*DD);
            float4 v = f4[lane];
            acc.x = fmaf(wj, v.x, acc.x);
            acc.y = fmaf(wj, v.y, acc.y);
            acc.z = fmaf(wj, v.z, acc.z);
            acc.w = fmaf(wj, v.w, acc.w);
        }
        ((float4*)(out + (size_t)r*DD))[lane] = acc;
    }
}

extern "C" void kernel_launch(void* const* d_in, const int* in_sizes, int n_in,
                              void* d_out, int out_size) {
    const float*  feats = (const float*)d_in[0];
    const float2* slocs = (const float2*)d_in[1];
    const float2* tlocs = (const float2*)d_in[2];
    float* out = (float*)d_out;

    int nb = (BB*NN + 255) / 256;
    k_count<<<nb, 256>>>(slocs);
    k_scan<<<BB, 512>>>();
    k_fill<<<nb, 256>>>(slocs);
    k_topk<<<(BB*MM)/TK_WARPS, TK_WARPS*32>>>(tlocs);
    k_tscan<<<BB, 1024>>>();
    k_tfill<<<(BB*MM*KK)/256, 256>>>();
    k_sink<<<NBLK, NTHR>>>(feats, out);
}

// round 5
// speedup vs baseline: 1.1128x; 1.1128x over previous
#include <cuda_runtime.h>

#define BB 4
#define NN 4096
#define MM 4096
#define DD 128
#define KK 64
#define GC 20
#define NCELL (GC*GC)
#define TIE_CAP 96
#define NBLK 128
#define NTHR 1024
#define FULLM 0xffffffffu
#define TK_WARPS 8
#define TAU 0.012f
#define TSC (256.0f/TAU)

// scratch (static device globals — zero-initialized at module load)
__device__ int    g_cellCnt[BB*NCELL];
__device__ int    g_cellStart[BB*(NCELL+1)];
__device__ int    g_cursor[BB*NCELL];
__device__ float2 g_slocs[BB*NN];
__device__ int    g_sid[BB*NN];
__device__ int    g_idx[BB*MM*KK];
__device__ float  g_p[BB*MM*KK];
__device__ float  g_cs[3][BB*NN];
__device__ unsigned g_barcnt;
__device__ unsigned g_bargen;

__global__ void k_count(const float2* __restrict__ slocs) {
    int i = blockIdx.x*256 + threadIdx.x;
    if (i >= BB*NN) return;
    float2 p = slocs[i];
    int b = i / NN;
    int cx = min(GC-1, max(0, (int)(p.x * GC)));
    int cy = min(GC-1, max(0, (int)(p.y * GC)));
    atomicAdd(&g_cellCnt[b*NCELL + cy*GC + cx], 1);
}

__global__ void k_scan() {
    __shared__ int sc[512];
    int b = blockIdx.x, t = threadIdx.x;
    int v = (t < NCELL) ? g_cellCnt[b*NCELL + t] : 0;
    sc[t] = v;
    __syncthreads();
    for (int off = 1; off < 512; off <<= 1) {
        int x = (t >= off) ? sc[t-off] : 0;
        __syncthreads();
        sc[t] += x;
        __syncthreads();
    }
    if (t < NCELL) {
        int excl = sc[t] - v;
        g_cellStart[b*(NCELL+1) + t] = excl;
        g_cursor[b*NCELL + t] = excl;
        g_cellCnt[b*NCELL + t] = 0;          // self-clean for next replay
    }
    if (t == NCELL-1) g_cellStart[b*(NCELL+1) + NCELL] = sc[t];
}

__global__ void k_fill(const float2* __restrict__ slocs) {
    int i = blockIdx.x*256 + threadIdx.x;
    if (i >= BB*NN) return;
    float2 p = slocs[i];
    int b = i / NN, n = i - b*NN;
    int cx = min(GC-1, max(0, (int)(p.x * GC)));
    int cy = min(GC-1, max(0, (int)(p.y * GC)));
    int pos = atomicAdd(&g_cursor[b*NCELL + cy*GC + cx], 1);
    g_slocs[b*NN + pos] = p;
    g_sid[b*NN + pos] = n;
}

// ---------------------------------------------------------------------------
// top-k: warp per row, 2-pass recompute. Pass 1 = ballot-free per-lane
// counting + tau-restricted fine histogram. Pass 2 = emit via ballot prefix.
// ---------------------------------------------------------------------------
__global__ void __launch_bounds__(TK_WARPS*32) k_topk(const float2* __restrict__ tlocs) {
    __shared__ int            s_hist[TK_WARPS][256];
    __shared__ float          s_td[TK_WARPS][TIE_CAP];
    __shared__ unsigned short s_tj[TK_WARPS][TIE_CAP];

    int warp = threadIdx.x >> 5, lane = threadIdx.x & 31;
    int row = blockIdx.x*TK_WARPS + warp;
    int b = row >> 12;
    unsigned lmask = (1u << lane) - 1u;

    float2 t = tlocs[row];
    int cx = min(GC-1, max(0, (int)(t.x*GC)));
    int cy = min(GC-1, max(0, (int)(t.y*GC)));
    int x0 = max(cx-3, 0), x1 = min(cx+3, GC-1);
    int y0 = max(cy-3, 0), y1 = min(cy+3, GC-1);
    const int* cs = &g_cellStart[b*(NCELL+1)];
    const float2* sl = &g_slocs[b*NN];
    const int* sid = &g_sid[b*NN];
    int* hist = s_hist[warp];

    #pragma unroll
    for (int i = 0; i < 8; i++) hist[lane*8+i] = 0;
    __syncwarp();

    // ---- pass 1: ballot-free counting + tau-restricted histogram ----
    int cnt = 0, ctau = 0, ncov = 0;
    for (int yy = y0; yy <= y1; yy++) {
        int lo = cs[yy*GC + x0];
        int hi = cs[yy*GC + x1 + 1];
        for (int j = lo + lane; j < hi; j += 32) {
            float2 s = sl[j];
            float dx = t.x - s.x, dy = t.y - s.y;
            float d = fmaf(dy, dy, dx*dx);
            if (d < 0.04f)   cnt++;
            if (d < 0.0225f) ncov++;
            if (d < TAU) { ctau++; atomicAdd(&hist[min(255,(int)(d*TSC))], 1); }
        }
    }
    // warp-reduce the three counters
    #pragma unroll
    for (int o = 16; o; o >>= 1) {
        cnt  += __shfl_xor_sync(FULLM, cnt,  o);
        ctau += __shfl_xor_sync(FULLM, ctau, o);
        ncov += __shfl_xor_sync(FULLM, ncov, o);
    }

    bool fullscan = (ncov < KK);
    if (fullscan) {
        // rare: box coverage insufficient -> rescan all sources
        #pragma unroll
        for (int i = 0; i < 8; i++) hist[lane*8+i] = 0;
        __syncwarp();
        cnt = 0; ctau = 0;
        for (int j = lane; j < NN; j += 32) {
            float2 s = sl[j];
            float dx = t.x - s.x, dy = t.y - s.y;
            float d = fmaf(dy, dy, dx*dx);
            if (d < 0.04f) cnt++;
            if (d < TAU) { ctau++; atomicAdd(&hist[min(255,(int)(d*TSC))], 1); }
        }
        #pragma unroll
        for (int o = 16; o; o >>= 1) {
            cnt  += __shfl_xor_sync(FULLM, cnt,  o);
            ctau += __shfl_xor_sync(FULLM, ctau, o);
        }
    }
    __syncwarp();

    const float kInv = 99.9999f;   // 1/(EPSILON+1e-8)
    int*   oid = &g_idx[(size_t)row*KK];
    float* op  = &g_p[(size_t)row*KK];

    if (cnt <= KK) {
        // emit everything in traversal order, pad with zeros
        int pos = 0;
        int yA = fullscan ? 0 : y0, yB = fullscan ? 1 : (y1 - y0 + 1);
        for (int yi = 0; yi < yB; yi++) {
            int lo, hi;
            if (fullscan) { lo = 0; hi = NN; }
            else { int yy = yA + yi; lo = cs[yy*GC + x0]; hi = cs[yy*GC + x1 + 1]; }
            for (int base = lo; base < hi; base += 32) {
                int j = base + lane;
                float d = 1e9f;
                if (j < hi) {
                    float2 s = sl[j];
                    float dx = t.x - s.x, dy = t.y - s.y;
                    d = fmaf(dy, dy, dx*dx);
                }
                bool hit = d < 0.04f;
                unsigned bm = __ballot_sync(FULLM, hit);
                int p = pos + __popc(bm & lmask);
                if (hit && p < KK) { oid[p] = sid[j]; op[p] = __expf(-d*kInv); }
                pos += __popc(bm);
            }
        }
        for (int p = pos + lane; p < KK; p += 32) { oid[p] = 0; op[p] = 0.0f; }
        return;
    }

    float hsc, hbound;
    if (ctau >= KK) { hsc = TSC; hbound = TAU; }
    else {
        // boundary row: rebuild coarse histogram over full 0.04 range
        #pragma unroll
        for (int i = 0; i < 8; i++) hist[lane*8+i] = 0;
        __syncwarp();
        if (!fullscan) {
            for (int yy = y0; yy <= y1; yy++) {
                int lo = cs[yy*GC + x0];
                int hi = cs[yy*GC + x1 + 1];
                for (int j = lo + lane; j < hi; j += 32) {
                    float2 s = sl[j];
                    float dx = t.x - s.x, dy = t.y - s.y;
                    float d = fmaf(dy, dy, dx*dx);
                    if (d < 0.04f) atomicAdd(&hist[min(255,(int)(d*6400.0f))], 1);
                }
            }
        } else {
            for (int j = lane; j < NN; j += 32) {
                float2 s = sl[j];
                float dx = t.x - s.x, dy = t.y - s.y;
                float d = fmaf(dy, dy, dx*dx);
                if (d < 0.04f) atomicAdd(&hist[min(255,(int)(d*6400.0f))], 1);
            }
        }
        __syncwarp();
        hsc = 6400.0f; hbound = 0.04f;
    }

    // ---- threshold bin via warp prefix over 256 bins ----
    int h[8]; int part = 0;
    #pragma unroll
    for (int i = 0; i < 8; i++) { h[i] = hist[lane*8+i]; part += h[i]; }
    int inc = part;
    #pragma unroll
    for (int off = 1; off < 32; off <<= 1) {
        int y = __shfl_up_sync(FULLM, inc, off);
        if (lane >= off) inc += y;
    }
    int exc = inc - part;
    int tb = -1, r = 0;
    if (exc < KK && KK <= inc) {
        int c = exc;
        #pragma unroll
        for (int i = 0; i < 8; i++) {
            if (tb < 0) {
                if (c + h[i] >= KK) { tb = lane*8 + i; r = KK - c; }
                else c += h[i];
            }
        }
    }
    int srcl = __ffs(__ballot_sync(FULLM, tb >= 0)) - 1;
    tb = __shfl_sync(FULLM, tb, srcl);
    r  = __shfl_sync(FULLM, r,  srcl);

    // ---- pass 2: recompute, emit below-threshold, collect ties ----
    int pos = 0, ntie = 0;
    int yB = fullscan ? 1 : (y1 - y0 + 1);
    for (int yi = 0; yi < yB; yi++) {
        int lo, hi;
        if (fullscan) { lo = 0; hi = NN; }
        else { int yy = y0 + yi; lo = cs[yy*GC + x0]; hi = cs[yy*GC + x1 + 1]; }
        for (int base = lo; base < hi; base += 32) {
            int j = base + lane;
            float d = 1e9f;
            if (j < hi) {
                float2 s = sl[j];
                float dx = t.x - s.x, dy = t.y - s.y;
                d = fmaf(dy, dy, dx*dx);
            }
            int bn = (d < hbound) ? min(255,(int)(d*hsc)) : 300;
            bool sel = bn < tb, tie = bn == tb;
            unsigned bs = __ballot_sync(FULLM, sel);
            int p = pos + __popc(bs & lmask);
            if (sel) { oid[p] = sid[j]; op[p] = __expf(-d*kInv); }
            pos += __popc(bs);
            unsigned bt = __ballot_sync(FULLM, tie);
            int q = ntie + __popc(bt & lmask);
            if (tie && q < TIE_CAP) { s_td[warp][q] = d; s_tj[warp][q] = (unsigned short)j; }
            ntie += __popc(bt);
        }
    }
    __syncwarp();
    if (lane == 0) {
        int nt = min(ntie, TIE_CAP);
        int rr = min(r, nt);
        for (int k2 = 0; k2 < rr; k2++) {
            float best = 1e30f; int bj = 0;
            for (int j2 = 0; j2 < nt; j2++)
                if (s_td[warp][j2] < best) { best = s_td[warp][j2]; bj = j2; }
            oid[pos+k2] = sid[s_tj[warp][bj]];
            op[pos+k2]  = __expf(-best*kInv);
            s_td[warp][bj] = 1e30f;
        }
        for (int k2 = rr; k2 < r; k2++) { oid[pos+k2] = 0; op[pos+k2] = 0.0f; }
    }
}

// ---------------------------------------------------------------------------
// persistent Sinkhorn: atomic scatter + smem-staged reciprocal tables,
// 1 grid barrier per iteration, fused output GEMM.
// ---------------------------------------------------------------------------
__device__ __forceinline__ unsigned ld_acq(const unsigned* p) {
    unsigned v;
    asm volatile("ld.acquire.gpu.u32 %0, [%1];" : "=r"(v) : "l"(p) : "memory");
    return v;
}
__device__ __forceinline__ void st_rel(unsigned* p, unsigned v) {
    asm volatile("st.release.gpu.u32 [%0], %1;" :: "l"(p), "r"(v) : "memory");
}
__device__ __forceinline__ void gridbar() {
    __syncthreads();
    if (threadIdx.x == 0) {
        unsigned g = ld_acq(&g_bargen);
        __threadfence();
        if (atomicAdd(&g_barcnt, 1u) == NBLK - 1) {
            g_barcnt = 0;
            st_rel(&g_bargen, g + 1);
        } else {
            while (ld_acq(&g_bargen) == g) { __nanosleep(20); }
        }
    }
    __syncthreads();
}

__global__ void __launch_bounds__(NTHR, 1) k_sink(const float* __restrict__ feats,
                                                  float* __restrict__ out) {
    __shared__ float s_tab[NN];
    int lane = threadIdx.x & 31;
    int warp = threadIdx.x >> 5;        // 0..31
    int blk = blockIdx.x;               // 0..127  (32 blocks per batch)
    int b = blk >> 5;
    int bofs = b * NN;
    int rbase = blk*128 + warp*4;       // global row base (batch-aligned)
    int zofs = bofs + (blk & 31)*128;   // this block's 128-column zero slice

    int   i0[4], i1[4];
    float p0[4], p1[4], eu[4];

    #pragma unroll
    for (int k = 0; k < 4; k++) {
        int r = rbase + k;
        const int*   ri = &g_idx[(size_t)r*KK];
        const float* rp = &g_p[(size_t)r*KK];
        i0[k] = ri[lane];   i1[k] = ri[lane+32];
        p0[k] = rp[lane];   p1[k] = rp[lane+32];
    }

    // replay-determinism: zero the t=0 write buffer, then sync the grid
    if (threadIdx.x < 128) g_cs[1][zofs + threadIdx.x] = 0.0f;
    gridbar();

    #pragma unroll 1
    for (int t = 0; t < 8; t++) {
        const float* crd = g_cs[t % 3];
        float*       cwr = g_cs[(t+1) % 3];
        float*       czr = g_cs[(t+2) % 3];
        // stage reciprocal colsum table (ev) in smem
        if (t > 0) {
            #pragma unroll
            for (int x = 0; x < NN/NTHR; x++) {
                float c = __ldcg(&crd[bofs + threadIdx.x + x*NTHR]);
                s_tab[threadIdx.x + x*NTHR] = (c > 0.0f) ? 1.0f/c : 0.0f;
            }
            __syncthreads();
        }
        // zero next iteration's write buffer (disjoint from crd/cwr)
        if (threadIdx.x < 128) czr[zofs + threadIdx.x] = 0.0f;
        // u-phase + scatter
        #pragma unroll
        for (int k = 0; k < 4; k++) {
            float s;
            if (t == 0) s = p0[k] + p1[k];                 // ev == 1 initially
            else        s = p0[k]*s_tab[i0[k]] + p1[k]*s_tab[i1[k]];
            #pragma unroll
            for (int o = 16; o; o >>= 1) s += __shfl_xor_sync(FULLM, s, o);
            float e = (s > 0.0f) ? 1.0f/s : 0.0f;
            eu[k] = e;
            float w0 = p0[k]*e, w1 = p1[k]*e;
            if (w0 != 0.0f) atomicAdd(&cwr[bofs + i0[k]], w0);
            if (w1 != 0.0f) atomicAdd(&cwr[bofs + i1[k]], w1);
        }
        gridbar();
    }

    // ---- epilogue: out[r,:] = sum_j p_j*eu_r*ev_{i_j} * feats[i_j,:] ----
    {
        const float* evb = g_cs[2];     // cwr of final iteration (t=7)
        #pragma unroll
        for (int x = 0; x < NN/NTHR; x++) {
            float c = __ldcg(&evb[bofs + threadIdx.x + x*NTHR]);
            s_tab[threadIdx.x + x*NTHR] = (c > 0.0f) ? 1.0f/c : 0.0f;
        }
        __syncthreads();
    }
    const float* fb = feats + (size_t)b*NN*DD;
    #pragma unroll 1
    for (int k = 0; k < 4; k++) {
        int r = rbase + k;
        float w0 = p0[k]*eu[k]*s_tab[i0[k]];
        float w1 = p1[k]*eu[k]*s_tab[i1[k]];
        float4 acc = make_float4(0.f, 0.f, 0.f, 0.f);
        #pragma unroll 16
        for (int j = 0; j < KK; j++) {
            int src = j & 31;
            float wj = __shfl_sync(FULLM, (j < 32) ? w0 : w1, src);
            int   ij = __shfl_sync(FULLM, (j < 32) ? i0[k] : i1[k], src);
            const float4* f4 = (const float4*)(fb + (size_t)ij*DD);
            float4 v = f4[lane];
            acc.x = fmaf(wj, v.x, acc.x);
            acc.y = fmaf(wj, v.y, acc.y);
            acc.z = fmaf(wj, v.z, acc.z);
            acc.w = fmaf(wj, v.w, acc.w);
        }
        ((float4*)(out + (size_t)r*DD))[lane] = acc;
    }
}

extern "C" void kernel_launch(void* const* d_in, const int* in_sizes, int n_in,
                              void* d_out, int out_size) {
    const float*  feats = (const float*)d_in[0];
    const float2* slocs = (const float2*)d_in[1];
    const float2* tlocs = (const float2*)d_in[2];
    float* out = (float*)d_out;

    int nb = (BB*NN + 255) / 256;
    k_count<<<nb, 256>>>(slocs);
    k_scan<<<BB, 512>>>();
    k_fill<<<nb, 256>>>(slocs);
    k_topk<<<(BB*MM)/TK_WARPS, TK_WARPS*32>>>(tlocs);
    k_sink<<<NBLK, NTHR>>>(feats, out);
}

// round 6
// speedup vs baseline: 1.8730x; 1.6831x over previous
#include <cuda_runtime.h>

#define BB 4
#define NN 4096
#define MM 4096
#define DD 128
#define KK 64
#define GC 20
#define NCELL (GC*GC)
#define TIE_CAP 96
#define NBLK 128
#define NTHR 1024
#define FULLM 0xffffffffu
#define TK_WARPS 8
#define TAU 0.012f
#define TSC (256.0f/TAU)

// scratch (static device globals — zero-initialized at module load)
__device__ int    g_cellCnt[BB*NCELL];
__device__ int    g_cellStart[BB*(NCELL+1)];
__device__ int    g_cursor[BB*NCELL];
__device__ float2 g_slocs[BB*NN];
__device__ int    g_sid[BB*NN];
__device__ int    g_idx[BB*MM*KK];
__device__ float  g_p[BB*MM*KK];
__device__ float  g_part[NBLK*NN];     // per-block partial column sums
__device__ float  g_ev[BB*NN];         // reciprocal colsum table
__device__ unsigned g_barcnt;
__device__ unsigned g_bargen;

__global__ void k_count(const float2* __restrict__ slocs) {
    int i = blockIdx.x*256 + threadIdx.x;
    if (i >= BB*NN) return;
    float2 p = slocs[i];
    int b = i / NN;
    int cx = min(GC-1, max(0, (int)(p.x * GC)));
    int cy = min(GC-1, max(0, (int)(p.y * GC)));
    atomicAdd(&g_cellCnt[b*NCELL + cy*GC + cx], 1);
}

__global__ void k_scan() {
    __shared__ int sc[512];
    int b = blockIdx.x, t = threadIdx.x;
    int v = (t < NCELL) ? g_cellCnt[b*NCELL + t] : 0;
    sc[t] = v;
    __syncthreads();
    for (int off = 1; off < 512; off <<= 1) {
        int x = (t >= off) ? sc[t-off] : 0;
        __syncthreads();
        sc[t] += x;
        __syncthreads();
    }
    if (t < NCELL) {
        int excl = sc[t] - v;
        g_cellStart[b*(NCELL+1) + t] = excl;
        g_cursor[b*NCELL + t] = excl;
        g_cellCnt[b*NCELL + t] = 0;          // self-clean for next replay
    }
    if (t == NCELL-1) g_cellStart[b*(NCELL+1) + NCELL] = sc[t];
}

__global__ void k_fill(const float2* __restrict__ slocs) {
    int i = blockIdx.x*256 + threadIdx.x;
    if (i >= BB*NN) return;
    float2 p = slocs[i];
    int b = i / NN, n = i - b*NN;
    int cx = min(GC-1, max(0, (int)(p.x * GC)));
    int cy = min(GC-1, max(0, (int)(p.y * GC)));
    int pos = atomicAdd(&g_cursor[b*NCELL + cy*GC + cx], 1);
    g_slocs[b*NN + pos] = p;
    g_sid[b*NN + pos] = n;
}

// ---------------------------------------------------------------------------
// top-k: warp per row, 2-pass recompute (unchanged from R5 — hit prediction)
// ---------------------------------------------------------------------------
__global__ void __launch_bounds__(TK_WARPS*32) k_topk(const float2* __restrict__ tlocs) {
    __shared__ int            s_hist[TK_WARPS][256];
    __shared__ float          s_td[TK_WARPS][TIE_CAP];
    __shared__ unsigned short s_tj[TK_WARPS][TIE_CAP];

    int warp = threadIdx.x >> 5, lane = threadIdx.x & 31;
    int row = blockIdx.x*TK_WARPS + warp;
    int b = row >> 12;
    unsigned lmask = (1u << lane) - 1u;

    float2 t = tlocs[row];
    int cx = min(GC-1, max(0, (int)(t.x*GC)));
    int cy = min(GC-1, max(0, (int)(t.y*GC)));
    int x0 = max(cx-3, 0), x1 = min(cx+3, GC-1);
    int y0 = max(cy-3, 0), y1 = min(cy+3, GC-1);
    const int* cs = &g_cellStart[b*(NCELL+1)];
    const float2* sl = &g_slocs[b*NN];
    const int* sid = &g_sid[b*NN];
    int* hist = s_hist[warp];

    #pragma unroll
    for (int i = 0; i < 8; i++) hist[lane*8+i] = 0;
    __syncwarp();

    int cnt = 0, ctau = 0, ncov = 0;
    for (int yy = y0; yy <= y1; yy++) {
        int lo = cs[yy*GC + x0];
        int hi = cs[yy*GC + x1 + 1];
        for (int j = lo + lane; j < hi; j += 32) {
            float2 s = sl[j];
            float dx = t.x - s.x, dy = t.y - s.y;
            float d = fmaf(dy, dy, dx*dx);
            if (d < 0.04f)   cnt++;
            if (d < 0.0225f) ncov++;
            if (d < TAU) { ctau++; atomicAdd(&hist[min(255,(int)(d*TSC))], 1); }
        }
    }
    #pragma unroll
    for (int o = 16; o; o >>= 1) {
        cnt  += __shfl_xor_sync(FULLM, cnt,  o);
        ctau += __shfl_xor_sync(FULLM, ctau, o);
        ncov += __shfl_xor_sync(FULLM, ncov, o);
    }

    bool fullscan = (ncov < KK);
    if (fullscan) {
        #pragma unroll
        for (int i = 0; i < 8; i++) hist[lane*8+i] = 0;
        __syncwarp();
        cnt = 0; ctau = 0;
        for (int j = lane; j < NN; j += 32) {
            float2 s = sl[j];
            float dx = t.x - s.x, dy = t.y - s.y;
            float d = fmaf(dy, dy, dx*dx);
            if (d < 0.04f) cnt++;
            if (d < TAU) { ctau++; atomicAdd(&hist[min(255,(int)(d*TSC))], 1); }
        }
        #pragma unroll
        for (int o = 16; o; o >>= 1) {
            cnt  += __shfl_xor_sync(FULLM, cnt,  o);
            ctau += __shfl_xor_sync(FULLM, ctau, o);
        }
    }
    __syncwarp();

    const float kInv = 99.9999f;   // 1/(EPSILON+1e-8)
    int*   oid = &g_idx[(size_t)row*KK];
    float* op  = &g_p[(size_t)row*KK];

    if (cnt <= KK) {
        int pos = 0;
        int yB = fullscan ? 1 : (y1 - y0 + 1);
        for (int yi = 0; yi < yB; yi++) {
            int lo, hi;
            if (fullscan) { lo = 0; hi = NN; }
            else { int yy = y0 + yi; lo = cs[yy*GC + x0]; hi = cs[yy*GC + x1 + 1]; }
            for (int base = lo; base < hi; base += 32) {
                int j = base + lane;
                float d = 1e9f;
                if (j < hi) {
                    float2 s = sl[j];
                    float dx = t.x - s.x, dy = t.y - s.y;
                    d = fmaf(dy, dy, dx*dx);
                }
                bool hit = d < 0.04f;
                unsigned bm = __ballot_sync(FULLM, hit);
                int p = pos + __popc(bm & lmask);
                if (hit && p < KK) { oid[p] = sid[j]; op[p] = __expf(-d*kInv); }
                pos += __popc(bm);
            }
        }
        for (int p = pos + lane; p < KK; p += 32) { oid[p] = 0; op[p] = 0.0f; }
        return;
    }

    float hsc, hbound;
    if (ctau >= KK) { hsc = TSC; hbound = TAU; }
    else {
        #pragma unroll
        for (int i = 0; i < 8; i++) hist[lane*8+i] = 0;
        __syncwarp();
        if (!fullscan) {
            for (int yy = y0; yy <= y1; yy++) {
                int lo = cs[yy*GC + x0];
                int hi = cs[yy*GC + x1 + 1];
                for (int j = lo + lane; j < hi; j += 32) {
                    float2 s = sl[j];
                    float dx = t.x - s.x, dy = t.y - s.y;
                    float d = fmaf(dy, dy, dx*dx);
                    if (d < 0.04f) atomicAdd(&hist[min(255,(int)(d*6400.0f))], 1);
                }
            }
        } else {
            for (int j = lane; j < NN; j += 32) {
                float2 s = sl[j];
                float dx = t.x - s.x, dy = t.y - s.y;
                float d = fmaf(dy, dy, dx*dx);
                if (d < 0.04f) atomicAdd(&hist[min(255,(int)(d*6400.0f))], 1);
            }
        }
        __syncwarp();
        hsc = 6400.0f; hbound = 0.04f;
    }

    int h[8]; int part = 0;
    #pragma unroll
    for (int i = 0; i < 8; i++) { h[i] = hist[lane*8+i]; part += h[i]; }
    int inc = part;
    #pragma unroll
    for (int off = 1; off < 32; off <<= 1) {
        int y = __shfl_up_sync(FULLM, inc, off);
        if (lane >= off) inc += y;
    }
    int exc = inc - part;
    int tb = -1, r = 0;
    if (exc < KK && KK <= inc) {
        int c = exc;
        #pragma unroll
        for (int i = 0; i < 8; i++) {
            if (tb < 0) {
                if (c + h[i] >= KK) { tb = lane*8 + i; r = KK - c; }
                else c += h[i];
            }
        }
    }
    int srcl = __ffs(__ballot_sync(FULLM, tb >= 0)) - 1;
    tb = __shfl_sync(FULLM, tb, srcl);
    r  = __shfl_sync(FULLM, r,  srcl);

    int pos = 0, ntie = 0;
    int yB = fullscan ? 1 : (y1 - y0 + 1);
    for (int yi = 0; yi < yB; yi++) {
        int lo, hi;
        if (fullscan) { lo = 0; hi = NN; }
        else { int yy = y0 + yi; lo = cs[yy*GC + x0]; hi = cs[yy*GC + x1 + 1]; }
        for (int base = lo; base < hi; base += 32) {
            int j = base + lane;
            float d = 1e9f;
            if (j < hi) {
                float2 s = sl[j];
                float dx = t.x - s.x, dy = t.y - s.y;
                d = fmaf(dy, dy, dx*dx);
            }
            int bn = (d < hbound) ? min(255,(int)(d*hsc)) : 300;
            bool sel = bn < tb, tie = bn == tb;
            unsigned bs = __ballot_sync(FULLM, sel);
            int p = pos + __popc(bs & lmask);
            if (sel) { oid[p] = sid[j]; op[p] = __expf(-d*kInv); }
            pos += __popc(bs);
            unsigned bt = __ballot_sync(FULLM, tie);
            int q = ntie + __popc(bt & lmask);
            if (tie && q < TIE_CAP) { s_td[warp][q] = d; s_tj[warp][q] = (unsigned short)j; }
            ntie += __popc(bt);
        }
    }
    __syncwarp();
    if (lane == 0) {
        int nt = min(ntie, TIE_CAP);
        int rr = min(r, nt);
        for (int k2 = 0; k2 < rr; k2++) {
            float best = 1e30f; int bj = 0;
            for (int j2 = 0; j2 < nt; j2++)
                if (s_td[warp][j2] < best) { best = s_td[warp][j2]; bj = j2; }
            oid[pos+k2] = sid[s_tj[warp][bj]];
            op[pos+k2]  = __expf(-best*kInv);
            s_td[warp][bj] = 1e30f;
        }
        for (int k2 = rr; k2 < r; k2++) { oid[pos+k2] = 0; op[pos+k2] = 0.0f; }
    }
}

// ---------------------------------------------------------------------------
// persistent Sinkhorn: NO global atomics. Per-block smem partial colsums ->
// coalesced partial dump -> cross-block tree reduce. 2 barriers/iter.
// Fused output GEMM epilogue.
// ---------------------------------------------------------------------------
__device__ __forceinline__ unsigned ld_acq(const unsigned* p) {
    unsigned v;
    asm volatile("ld.acquire.gpu.u32 %0, [%1];" : "=r"(v) : "l"(p) : "memory");
    return v;
}
__device__ __forceinline__ void st_rel(unsigned* p, unsigned v) {
    asm volatile("st.release.gpu.u32 [%0], %1;" :: "l"(p), "r"(v) : "memory");
}
__device__ __forceinline__ void gridbar() {
    __syncthreads();
    if (threadIdx.x == 0) {
        unsigned g = ld_acq(&g_bargen);
        __threadfence();
        if (atomicAdd(&g_barcnt, 1u) == NBLK - 1) {
            g_barcnt = 0;
            st_rel(&g_bargen, g + 1);
        } else {
            while (ld_acq(&g_bargen) == g) { __nanosleep(20); }
        }
    }
    __syncthreads();
}

__global__ void __launch_bounds__(NTHR, 1) k_sink(const float* __restrict__ feats,
                                                  float* __restrict__ out) {
    __shared__ float s_tab[NN];      // reciprocal ev table
    __shared__ float s_acc[NN];      // partial colsum accumulator / reduce scratch
    int lane = threadIdx.x & 31;
    int warp = threadIdx.x >> 5;        // 0..31
    int blk = blockIdx.x;               // 0..127  (32 blocks per batch)
    int b = blk >> 5;
    int bofs = b * NN;
    int rbase = blk*128 + warp*4;       // global row base (batch-aligned)
    int zcol = (blk & 31)*128;          // owned 128-column slice within batch

    int   i0[4], i1[4];
    float p0[4], p1[4], eu[4];

    #pragma unroll
    for (int k = 0; k < 4; k++) {
        int r = rbase + k;
        const int*   ri = &g_idx[(size_t)r*KK];
        const float* rp = &g_p[(size_t)r*KK];
        i0[k] = ri[lane];   i1[k] = ri[lane+32];
        p0[k] = rp[lane];   p1[k] = rp[lane+32];
    }

    #pragma unroll 1
    for (int t = 0; t < 8; t++) {
        // stage reciprocal ev table + zero partial accumulator
        if (t > 0) {
            #pragma unroll
            for (int x = 0; x < NN/NTHR; x++)
                s_tab[threadIdx.x + x*NTHR] = __ldcg(&g_ev[bofs + threadIdx.x + x*NTHR]);
        }
        #pragma unroll
        for (int x = 0; x < NN/NTHR; x++)
            s_acc[threadIdx.x + x*NTHR] = 0.0f;
        __syncthreads();

        // u-phase + smem scatter
        #pragma unroll
        for (int k = 0; k < 4; k++) {
            float s;
            if (t == 0) s = p0[k] + p1[k];                 // ev == 1 initially
            else        s = p0[k]*s_tab[i0[k]] + p1[k]*s_tab[i1[k]];
            #pragma unroll
            for (int o = 16; o; o >>= 1) s += __shfl_xor_sync(FULLM, s, o);
            float e = (s > 0.0f) ? 1.0f/s : 0.0f;
            eu[k] = e;
            float w0 = p0[k]*e, w1 = p1[k]*e;
            if (w0 != 0.0f) atomicAdd(&s_acc[i0[k]], w0);
            if (w1 != 0.0f) atomicAdd(&s_acc[i1[k]], w1);
        }
        __syncthreads();

        // dump partial (coalesced)
        #pragma unroll
        for (int x = 0; x < NN/NTHR; x++)
            g_part[(size_t)blk*NN + threadIdx.x + x*NTHR] = s_acc[threadIdx.x + x*NTHR];
        gridbar();

        // reduce 32 partials for owned columns; store reciprocal ev
        {
            int p8 = threadIdx.x >> 7;     // 0..7
            int c  = threadIdx.x & 127;
            float s = 0.0f;
            #pragma unroll
            for (int q = 0; q < 4; q++)
                s += __ldcg(&g_part[(size_t)(b*32 + p8 + q*8)*NN + zcol + c]);
            s_acc[p8*128 + c] = s;
            __syncthreads();
            if (threadIdx.x < 128) {
                float tot = 0.0f;
                #pragma unroll
                for (int g2 = 0; g2 < 8; g2++) tot += s_acc[g2*128 + threadIdx.x];
                g_ev[bofs + zcol + threadIdx.x] = (tot > 0.0f) ? 1.0f/tot : 0.0f;
            }
        }
        gridbar();
    }

    // ---- epilogue: out[r,:] = sum_j p_j*eu_r*ev_{i_j} * feats[i_j,:] ----
    #pragma unroll
    for (int x = 0; x < NN/NTHR; x++)
        s_tab[threadIdx.x + x*NTHR] = __ldcg(&g_ev[bofs + threadIdx.x + x*NTHR]);
    __syncthreads();
    const float* fb = feats + (size_t)b*NN*DD;
    #pragma unroll 1
    for (int k = 0; k < 4; k++) {
        int r = rbase + k;
        float w0 = p0[k]*eu[k]*s_tab[i0[k]];
        float w1 = p1[k]*eu[k]*s_tab[i1[k]];
        float4 acc = make_float4(0.f, 0.f, 0.f, 0.f);
        #pragma unroll 16
        for (int j = 0; j < KK; j++) {
            int src = j & 31;
            float wj = __shfl_sync(FULLM, (j < 32) ? w0 : w1, src);
            int   ij = __shfl_sync(FULLM, (j < 32) ? i0[k] : i1[k], src);
            const float4* f4 = (const float4*)(fb + (size_t)ij*DD);
            float4 v = f4[lane];
            acc.x = fmaf(wj, v.x, acc.x);
            acc.y = fmaf(wj, v.y, acc.y);
            acc.z = fmaf(wj, v.z, acc.z);
            acc.w = fmaf(wj, v.w, acc.w);
        }
        ((float4*)(out + (size_t)r*DD))[lane] = acc;
    }
}

extern "C" void kernel_launch(void* const* d_in, const int* in_sizes, int n_in,
                              void* d_out, int out_size) {
    const float*  feats = (const float*)d_in[0];
    const float2* slocs = (const float2*)d_in[1];
    const float2* tlocs = (const float2*)d_in[2];
    float* out = (float*)d_out;

    int nb = (BB*NN + 255) / 256;
    k_count<<<nb, 256>>>(slocs);
    k_scan<<<BB, 512>>>();
    k_fill<<<nb, 256>>>(slocs);
    k_topk<<<(BB*MM)/TK_WARPS, TK_WARPS*32>>>(tlocs);
    k_sink<<<NBLK, NTHR>>>(feats, out);
}

// round 7
// speedup vs baseline: 2.0424x; 1.0905x over previous
#include <cuda_runtime.h>
#include <cuda_fp16.h>

#define BB 4
#define NN 4096
#define MM 4096
#define DD 128
#define KK 64
#define GC 20
#define GCI (1.0f/GC)
#define NCELL (GC*GC)
#define TIE_CAP 96
#define NBLK 128
#define NTHR 1024
#define FULLM 0xffffffffu
#define TK_WARPS 8
#define TAU 0.012f
#define TSC (256.0f/TAU)
#define R1SQ 0.0225f

// scratch (static device globals — zero-initialized at module load)
__device__ int    g_cellCnt[BB*NCELL];
__device__ int    g_cellStart[BB*(NCELL+1)];
__device__ int    g_cursor[BB*NCELL];
__device__ float2 g_slocs[BB*NN];
__device__ int    g_sid[BB*NN];
__device__ int    g_idx[BB*MM*KK];
__device__ float  g_p[BB*MM*KK];
__device__ float  g_part[NBLK*NN];     // per-block partial column sums
__device__ float  g_ev[BB*NN];         // reciprocal colsum table
__device__ __half g_fh[BB*NN*DD];      // fp16 features
__device__ unsigned g_barcnt;
__device__ unsigned g_bargen;

__global__ void k_count(const float2* __restrict__ slocs) {
    int i = blockIdx.x*256 + threadIdx.x;
    if (i >= BB*NN) return;
    float2 p = slocs[i];
    int b = i / NN;
    int cx = min(GC-1, max(0, (int)(p.x * GC)));
    int cy = min(GC-1, max(0, (int)(p.y * GC)));
    atomicAdd(&g_cellCnt[b*NCELL + cy*GC + cx], 1);
}

__global__ void k_scan() {
    __shared__ int sc[512];
    int b = blockIdx.x, t = threadIdx.x;
    int v = (t < NCELL) ? g_cellCnt[b*NCELL + t] : 0;
    sc[t] = v;
    __syncthreads();
    for (int off = 1; off < 512; off <<= 1) {
        int x = (t >= off) ? sc[t-off] : 0;
        __syncthreads();
        sc[t] += x;
        __syncthreads();
    }
    if (t < NCELL) {
        int excl = sc[t] - v;
        g_cellStart[b*(NCELL+1) + t] = excl;
        g_cursor[b*NCELL + t] = excl;
        g_cellCnt[b*NCELL + t] = 0;          // self-clean for next replay
    }
    if (t == NCELL-1) g_cellStart[b*(NCELL+1) + NCELL] = sc[t];
}

__global__ void k_fill(const float2* __restrict__ slocs) {
    int i = blockIdx.x*256 + threadIdx.x;
    if (i >= BB*NN) return;
    float2 p = slocs[i];
    int b = i / NN, n = i - b*NN;
    int cx = min(GC-1, max(0, (int)(p.x * GC)));
    int cy = min(GC-1, max(0, (int)(p.y * GC)));
    int pos = atomicAdd(&g_cursor[b*NCELL + cy*GC + cx], 1);
    g_slocs[b*NN + pos] = p;
    g_sid[b*NN + pos] = n;
}

__global__ void k_half(const float* __restrict__ feats) {
    int i = blockIdx.x*256 + threadIdx.x;     // over BB*NN*DD/4
    float4 v = ((const float4*)feats)[i];
    __half2 a = __floats2half2_rn(v.x, v.y);
    __half2 c = __floats2half2_rn(v.z, v.w);
    uint2 w;
    w.x = *(unsigned*)&a;
    w.y = *(unsigned*)&c;
    ((uint2*)g_fh)[i] = w;
}

// ---------------------------------------------------------------------------
// top-k: warp per row, 2-pass recompute with per-row x-range circle pruning.
// ---------------------------------------------------------------------------
__global__ void __launch_bounds__(TK_WARPS*32) k_topk(const float2* __restrict__ tlocs) {
    __shared__ int            s_hist[TK_WARPS][256];
    __shared__ float          s_td[TK_WARPS][TIE_CAP];
    __shared__ unsigned short s_tj[TK_WARPS][TIE_CAP];

    int warp = threadIdx.x >> 5, lane = threadIdx.x & 31;
    int row = blockIdx.x*TK_WARPS + warp;
    int b = row >> 12;
    unsigned lmask = (1u << lane) - 1u;

    float2 t = tlocs[row];
    int cx = min(GC-1, max(0, (int)(t.x*GC)));
    int cy = min(GC-1, max(0, (int)(t.y*GC)));
    int x0 = max(cx-3, 0), x1 = min(cx+3, GC-1);
    int y0 = max(cy-3, 0), y1 = min(cy+3, GC-1);
    const int* cs = &g_cellStart[b*(NCELL+1)];
    const float2* sl = &g_slocs[b*NN];
    const int* sid = &g_sid[b*NN];
    int* hist = s_hist[warp];

    #pragma unroll
    for (int i = 0; i < 8; i++) hist[lane*8+i] = 0;
    __syncwarp();

    // ---- pass 1: pruned to 0.0225-circle; count ncov/ctau + fine hist ----
    int ncov = 0, ctau = 0;
    for (int yy = y0; yy <= y1; yy++) {
        float ylo = yy*GCI;
        float dyv = fmaxf(0.0f, fmaxf(ylo - t.y, t.y - (ylo+GCI)));
        float bud = R1SQ - dyv*dyv;
        if (bud <= 0.0f) continue;
        float rx = sqrtf(bud);
        int xlo = max(x0, (int)((t.x - rx)*GC));
        int xhi = min(x1, (int)((t.x + rx)*GC));
        int lo = cs[yy*GC + xlo];
        int hi = cs[yy*GC + xhi + 1];
        for (int j = lo + lane; j < hi; j += 32) {
            float2 s = sl[j];
            float dx = t.x - s.x, dy = t.y - s.y;
            float d = fmaf(dy, dy, dx*dx);
            if (d < R1SQ) ncov++;
            if (d < TAU) { ctau++; atomicAdd(&hist[min(255,(int)(d*TSC))], 1); }
        }
    }
    #pragma unroll
    for (int o = 16; o; o >>= 1) {
        ncov += __shfl_xor_sync(FULLM, ncov, o);
        ctau += __shfl_xor_sync(FULLM, ctau, o);
    }

    const float kInv = 99.9999f;   // 1/(EPSILON+1e-8)
    int*   oid = &g_idx[(size_t)row*KK];
    float* op  = &g_p[(size_t)row*KK];

    int mode;                       // 0 = fine, 1 = coarse box, 2 = fullscan
    float hsc, hbound;
    if (ctau >= KK) { mode = 0; hsc = TSC; hbound = TAU; }
    else {
        mode = (ncov < KK) ? 2 : 1;
        // rebuild coarse histogram (unpruned) + count cnt
        #pragma unroll
        for (int i = 0; i < 8; i++) hist[lane*8+i] = 0;
        __syncwarp();
        int cnt = 0;
        if (mode == 1) {
            for (int yy = y0; yy <= y1; yy++) {
                int lo = cs[yy*GC + x0];
                int hi = cs[yy*GC + x1 + 1];
                for (int j = lo + lane; j < hi; j += 32) {
                    float2 s = sl[j];
                    float dx = t.x - s.x, dy = t.y - s.y;
                    float d = fmaf(dy, dy, dx*dx);
                    if (d < 0.04f) { cnt++; atomicAdd(&hist[min(255,(int)(d*6400.0f))], 1); }
                }
            }
        } else {
            for (int j = lane; j < NN; j += 32) {
                float2 s = sl[j];
                float dx = t.x - s.x, dy = t.y - s.y;
                float d = fmaf(dy, dy, dx*dx);
                if (d < 0.04f) { cnt++; atomicAdd(&hist[min(255,(int)(d*6400.0f))], 1); }
            }
        }
        #pragma unroll
        for (int o = 16; o; o >>= 1) cnt += __shfl_xor_sync(FULLM, cnt, o);
        hsc = 6400.0f; hbound = 0.04f;

        if (cnt <= KK) {
            // emit everything in traversal order, pad with zeros
            int pos = 0;
            int yB = (mode == 2) ? 1 : (y1 - y0 + 1);
            for (int yi = 0; yi < yB; yi++) {
                int lo, hi;
                if (mode == 2) { lo = 0; hi = NN; }
                else { int yy = y0 + yi; lo = cs[yy*GC + x0]; hi = cs[yy*GC + x1 + 1]; }
                for (int base = lo; base < hi; base += 32) {
                    int j = base + lane;
                    float d = 1e9f;
                    if (j < hi) {
                        float2 s = sl[j];
                        float dx = t.x - s.x, dy = t.y - s.y;
                        d = fmaf(dy, dy, dx*dx);
                    }
                    bool hit = d < 0.04f;
                    unsigned bm = __ballot_sync(FULLM, hit);
                    int p = pos + __popc(bm & lmask);
                    if (hit && p < KK) { oid[p] = sid[j]; op[p] = __expf(-d*kInv); }
                    pos += __popc(bm);
                }
            }
            for (int p = pos + lane; p < KK; p += 32) { oid[p] = 0; op[p] = 0.0f; }
            return;
        }
    }
    __syncwarp();

    // ---- threshold bin via warp prefix over 256 bins ----
    int h[8]; int part = 0;
    #pragma unroll
    for (int i = 0; i < 8; i++) { h[i] = hist[lane*8+i]; part += h[i]; }
    int inc = part;
    #pragma unroll
    for (int off = 1; off < 32; off <<= 1) {
        int y = __shfl_up_sync(FULLM, inc, off);
        if (lane >= off) inc += y;
    }
    int exc = inc - part;
    int tb = -1, r = 0;
    if (exc < KK && KK <= inc) {
        int c = exc;
        #pragma unroll
        for (int i = 0; i < 8; i++) {
            if (tb < 0) {
                if (c + h[i] >= KK) { tb = lane*8 + i; r = KK - c; }
                else c += h[i];
            }
        }
    }
    int srcl = __ffs(__ballot_sync(FULLM, tb >= 0)) - 1;
    tb = __shfl_sync(FULLM, tb, srcl);
    r  = __shfl_sync(FULLM, r,  srcl);
    float dmax = (float)(tb + 1) / hsc;     // all selected/tied have d < dmax

    // ---- pass 2: pruned to dmax-circle; emit + collect ties ----
    int pos = 0, ntie = 0;
    int Y0 = (mode == 2) ? 0 : y0, Y1 = (mode == 2) ? GC-1 : y1;
    int X0 = (mode == 2) ? 0 : x0, X1 = (mode == 2) ? GC-1 : x1;
    for (int yy = Y0; yy <= Y1; yy++) {
        float ylo = yy*GCI;
        float dyv = fmaxf(0.0f, fmaxf(ylo - t.y, t.y - (ylo+GCI)));
        float bud = dmax - dyv*dyv;
        if (bud <= 0.0f) continue;
        float rx = sqrtf(bud);
        int xlo = max(X0, (int)((t.x - rx)*GC));
        int xhi = min(X1, (int)((t.x + rx)*GC));
        int lo = cs[yy*GC + xlo];
        int hi = cs[yy*GC + xhi + 1];
        for (int base = lo; base < hi; base += 32) {
            int j = base + lane;
            float d = 1e9f;
            if (j < hi) {
                float2 s = sl[j];
                float dx = t.x - s.x, dy = t.y - s.y;
                d = fmaf(dy, dy, dx*dx);
            }
            int bn = (d < hbound) ? min(255,(int)(d*hsc)) : 300;
            bool sel = bn < tb, tie = bn == tb;
            unsigned bs = __ballot_sync(FULLM, sel);
            int p = pos + __popc(bs & lmask);
            if (sel) { oid[p] = sid[j]; op[p] = __expf(-d*kInv); }
            pos += __popc(bs);
            unsigned bt = __ballot_sync(FULLM, tie);
            int q = ntie + __popc(bt & lmask);
            if (tie && q < TIE_CAP) { s_td[warp][q] = d; s_tj[warp][q] = (unsigned short)j; }
            ntie += __popc(bt);
        }
    }
    __syncwarp();
    if (lane == 0) {
        int nt = min(ntie, TIE_CAP);
        int rr = min(r, nt);
        for (int k2 = 0; k2 < rr; k2++) {
            float best = 1e30f; int bj = 0;
            for (int j2 = 0; j2 < nt; j2++)
                if (s_td[warp][j2] < best) { best = s_td[warp][j2]; bj = j2; }
            oid[pos+k2] = sid[s_tj[warp][bj]];
            op[pos+k2]  = __expf(-best*kInv);
            s_td[warp][bj] = 1e30f;
        }
        for (int k2 = rr; k2 < r; k2++) { oid[pos+k2] = 0; op[pos+k2] = 0.0f; }
    }
}

// ---------------------------------------------------------------------------
// persistent Sinkhorn (two-level reduction, no global atomics) + fp16 epilogue
// ---------------------------------------------------------------------------
__device__ __forceinline__ unsigned ld_acq(const unsigned* p) {
    unsigned v;
    asm volatile("ld.acquire.gpu.u32 %0, [%1];" : "=r"(v) : "l"(p) : "memory");
    return v;
}
__device__ __forceinline__ void st_rel(unsigned* p, unsigned v) {
    asm volatile("st.release.gpu.u32 [%0], %1;" :: "l"(p), "r"(v) : "memory");
}
__device__ __forceinline__ void gridbar() {
    __syncthreads();
    if (threadIdx.x == 0) {
        unsigned g = ld_acq(&g_bargen);
        __threadfence();
        if (atomicAdd(&g_barcnt, 1u) == NBLK - 1) {
            g_barcnt = 0;
            st_rel(&g_bargen, g + 1);
        } else {
            while (ld_acq(&g_bargen) == g) {}
        }
    }
    __syncthreads();
}

__global__ void __launch_bounds__(NTHR, 1) k_sink(float* __restrict__ out) {
    __shared__ float s_tab[NN];      // reciprocal ev table
    __shared__ float s_acc[NN];      // partial colsum accumulator / reduce scratch
    int lane = threadIdx.x & 31;
    int warp = threadIdx.x >> 5;        // 0..31
    int blk = blockIdx.x;               // 0..127  (32 blocks per batch)
    int b = blk >> 5;
    int bofs = b * NN;
    int rbase = blk*128 + warp*4;       // global row base (batch-aligned)
    int zcol = (blk & 31)*128;          // owned 128-column slice within batch

    int   i0[4], i1[4];
    float p0[4], p1[4], eu[4];

    #pragma unroll
    for (int k = 0; k < 4; k++) {
        int r = rbase + k;
        const int*   ri = &g_idx[(size_t)r*KK];
        const float* rp = &g_p[(size_t)r*KK];
        i0[k] = ri[lane];   i1[k] = ri[lane+32];
        p0[k] = rp[lane];   p1[k] = rp[lane+32];
    }

    #pragma unroll 1
    for (int t = 0; t < 8; t++) {
        if (t > 0) {
            #pragma unroll
            for (int x = 0; x < NN/NTHR; x++)
                s_tab[threadIdx.x + x*NTHR] = __ldcg(&g_ev[bofs + threadIdx.x + x*NTHR]);
        }
        #pragma unroll
        for (int x = 0; x < NN/NTHR; x++)
            s_acc[threadIdx.x + x*NTHR] = 0.0f;
        __syncthreads();

        #pragma unroll
        for (int k = 0; k < 4; k++) {
            float s;
            if (t == 0) s = p0[k] + p1[k];                 // ev == 1 initially
            else        s = p0[k]*s_tab[i0[k]] + p1[k]*s_tab[i1[k]];
            #pragma unroll
            for (int o = 16; o; o >>= 1) s += __shfl_xor_sync(FULLM, s, o);
            float e = (s > 0.0f) ? 1.0f/s : 0.0f;
            eu[k] = e;
            float w0 = p0[k]*e, w1 = p1[k]*e;
            if (w0 != 0.0f) atomicAdd(&s_acc[i0[k]], w0);
            if (w1 != 0.0f) atomicAdd(&s_acc[i1[k]], w1);
        }
        __syncthreads();

        #pragma unroll
        for (int x = 0; x < NN/NTHR; x++)
            g_part[(size_t)blk*NN + threadIdx.x + x*NTHR] = s_acc[threadIdx.x + x*NTHR];
        gridbar();

        {
            int p8 = threadIdx.x >> 7;     // 0..7
            int c  = threadIdx.x & 127;
            float s = 0.0f;
            #pragma unroll
            for (int q = 0; q < 4; q++)
                s += __ldcg(&g_part[(size_t)(b*32 + p8 + q*8)*NN + zcol + c]);
            s_acc[p8*128 + c] = s;
            __syncthreads();
            if (threadIdx.x < 128) {
                float tot = 0.0f;
                #pragma unroll
                for (int g2 = 0; g2 < 8; g2++) tot += s_acc[g2*128 + threadIdx.x];
                g_ev[bofs + zcol + threadIdx.x] = (tot > 0.0f) ? 1.0f/tot : 0.0f;
            }
        }
        gridbar();
    }

    // ---- epilogue: fp16 feature gathers ----
    #pragma unroll
    for (int x = 0; x < NN/NTHR; x++)
        s_tab[threadIdx.x + x*NTHR] = __ldcg(&g_ev[bofs + threadIdx.x + x*NTHR]);
    __syncthreads();
    const __half* fh = g_fh + (size_t)b*NN*DD;
    #pragma unroll 1
    for (int k = 0; k < 4; k++) {
        int r = rbase + k;
        float w0 = p0[k]*eu[k]*s_tab[i0[k]];
        float w1 = p1[k]*eu[k]*s_tab[i1[k]];
        float4 acc = make_float4(0.f, 0.f, 0.f, 0.f);
        #pragma unroll 16
        for (int j = 0; j < KK; j++) {
            int src = j & 31;
            float wj = __shfl_sync(FULLM, (j < 32) ? w0 : w1, src);
            int   ij = __shfl_sync(FULLM, (j < 32) ? i0[k] : i1[k], src);
            uint2 v = ((const uint2*)(fh + (size_t)ij*DD))[lane];
            __half2 h0 = *(__half2*)&v.x;
            __half2 h1 = *(__half2*)&v.y;
            float2 f0 = __half22float2(h0);
            float2 f1 = __half22float2(h1);
            acc.x = fmaf(wj, f0.x, acc.x);
            acc.y = fmaf(wj, f0.y, acc.y);
            acc.z = fmaf(wj, f1.x, acc.z);
            acc.w = fmaf(wj, f1.y, acc.w);
        }
        ((float4*)(out + (size_t)r*DD))[lane] = acc;
    }
}

extern "C" void kernel_launch(void* const* d_in, const int* in_sizes, int n_in,
                              void* d_out, int out_size) {
    const float*  feats = (const float*)d_in[0];
    const float2* slocs = (const float2*)d_in[1];
    const float2* tlocs = (const float2*)d_in[2];
    float* out = (float*)d_out;

    int nb = (BB*NN + 255) / 256;
    k_count<<<nb, 256>>>(slocs);
    k_scan<<<BB, 512>>>();
    k_fill<<<nb, 256>>>(slocs);
    k_half<<<(BB*NN*DD/4)/256, 256>>>(feats);
    k_topk<<<(BB*MM)/TK_WARPS, TK_WARPS*32>>>(tlocs);
    k_sink<<<NBLK, NTHR>>>(out);
}

// round 8
// speedup vs baseline: 2.1001x; 1.0283x over previous
#include <cuda_runtime.h>
#include <cuda_fp16.h>

#define BB 4
#define NN 4096
#define MM 4096
#define DD 128
#define KK 64
#define GC 20
#define GCI (1.0f/GC)
#define NCELL (GC*GC)
#define TIE_CAP 96
#define NBLK 128
#define NTHR 1024
#define FULLM 0xffffffffu
#define TK_WARPS 8
#define TAU 0.012f
#define TSC (256.0f/TAU)
#define R1SQ 0.0225f

// scratch (static device globals — zero-initialized at module load)
__device__ int    g_cellStart[BB*(NCELL+1)];
__device__ float2 g_slocs[BB*NN];
__device__ int    g_sid[BB*NN];
__device__ int    g_idx[BB*MM*KK];
__device__ float  g_p[BB*MM*KK];
__device__ float  g_part[NBLK*NN];     // per-block partial column sums
__device__ float  g_ev[BB*NN];         // reciprocal colsum table
__device__ __half g_fh[BB*NN*DD];      // fp16 features
__device__ unsigned g_barcnt;
__device__ unsigned g_bargen;

// ---------------------------------------------------------------------------
// fused binning: count + scan + scatter, one block per batch, smem-only state
// ---------------------------------------------------------------------------
__global__ void __launch_bounds__(1024) k_bin(const float2* __restrict__ slocs) {
    __shared__ int s_cnt[NCELL];
    __shared__ int sc[512];
    __shared__ int s_cur[NCELL];
    int b = blockIdx.x, t = threadIdx.x;

    if (t < NCELL) s_cnt[t] = 0;
    __syncthreads();

    float2 p[4]; int cell[4];
    #pragma unroll
    for (int k = 0; k < 4; k++) {
        int i = t + k*1024;
        p[k] = slocs[b*NN + i];
        int cx = min(GC-1, max(0, (int)(p[k].x * GC)));
        int cy = min(GC-1, max(0, (int)(p[k].y * GC)));
        cell[k] = cy*GC + cx;
        atomicAdd(&s_cnt[cell[k]], 1);
    }
    __syncthreads();

    // inclusive scan over 400 cells (512-wide Hillis-Steele)
    if (t < 512) sc[t] = (t < NCELL) ? s_cnt[t] : 0;
    __syncthreads();
    for (int off = 1; off < 512; off <<= 1) {
        int x = (t < 512 && t >= off) ? sc[t-off] : 0;
        __syncthreads();
        if (t < 512) sc[t] += x;
        __syncthreads();
    }
    if (t < NCELL) {
        int excl = sc[t] - s_cnt[t];
        g_cellStart[b*(NCELL+1) + t] = excl;
        s_cur[t] = excl;
    }
    if (t == 0) g_cellStart[b*(NCELL+1) + NCELL] = NN;
    __syncthreads();

    #pragma unroll
    for (int k = 0; k < 4; k++) {
        int i = t + k*1024;
        int pos = atomicAdd(&s_cur[cell[k]], 1);
        g_slocs[b*NN + pos] = p[k];
        g_sid[b*NN + pos] = i;
    }
}

__global__ void k_half(const float* __restrict__ feats) {
    int i = blockIdx.x*256 + threadIdx.x;     // over BB*NN*DD/4
    float4 v = ((const float4*)feats)[i];
    __half2 a = __floats2half2_rn(v.x, v.y);
    __half2 c = __floats2half2_rn(v.z, v.w);
    uint2 w;
    w.x = *(unsigned*)&a;
    w.y = *(unsigned*)&c;
    ((uint2*)g_fh)[i] = w;
}

// ---------------------------------------------------------------------------
// top-k: warp per row. Pass 1 scans tau-circle only; coverage guards
// deferred to the rare coarse path. Pass 2 pruned to selection radius.
// ---------------------------------------------------------------------------
__global__ void __launch_bounds__(TK_WARPS*32) k_topk(const float2* __restrict__ tlocs) {
    __shared__ int            s_hist[TK_WARPS][256];
    __shared__ float          s_td[TK_WARPS][TIE_CAP];
    __shared__ unsigned short s_tj[TK_WARPS][TIE_CAP];

    int warp = threadIdx.x >> 5, lane = threadIdx.x & 31;
    int row = blockIdx.x*TK_WARPS + warp;
    int b = row >> 12;
    unsigned lmask = (1u << lane) - 1u;

    float2 t = tlocs[row];
    int cx = min(GC-1, max(0, (int)(t.x*GC)));
    int cy = min(GC-1, max(0, (int)(t.y*GC)));
    int x0 = max(cx-3, 0), x1 = min(cx+3, GC-1);
    int y0 = max(cy-3, 0), y1 = min(cy+3, GC-1);
    const int* cs = &g_cellStart[b*(NCELL+1)];
    const float2* sl = &g_slocs[b*NN];
    const int* sid = &g_sid[b*NN];
    int* hist = s_hist[warp];

    #pragma unroll
    for (int i = 0; i < 8; i++) hist[lane*8+i] = 0;
    __syncwarp();

    // ---- pass 1: scan tau-circle only; fine histogram ----
    int ctau = 0;
    for (int yy = y0; yy <= y1; yy++) {
        float ylo = yy*GCI;
        float dyv = fmaxf(0.0f, fmaxf(ylo - t.y, t.y - (ylo+GCI)));
        float bud = TAU - dyv*dyv;
        if (bud <= 0.0f) continue;
        float rx = sqrtf(bud);
        int xlo = max(x0, (int)((t.x - rx)*GC));
        int xhi = min(x1, (int)((t.x + rx)*GC));
        int lo = cs[yy*GC + xlo];
        int hi = cs[yy*GC + xhi + 1];
        for (int j = lo + lane; j < hi; j += 32) {
            float2 s = sl[j];
            float dx = t.x - s.x, dy = t.y - s.y;
            float d = fmaf(dy, dy, dx*dx);
            if (d < TAU) { ctau++; atomicAdd(&hist[min(255,(int)(d*TSC))], 1); }
        }
    }
    #pragma unroll
    for (int o = 16; o; o >>= 1) ctau += __shfl_xor_sync(FULLM, ctau, o);

    const float kInv = 99.9999f;   // 1/(EPSILON+1e-8)
    int*   oid = &g_idx[(size_t)row*KK];
    float* op  = &g_p[(size_t)row*KK];

    int mode;                       // 0 = fine tau, 1 = coarse box, 2 = fullscan
    float hsc, hbound;
    if (ctau >= KK) { mode = 0; hsc = TSC; hbound = TAU; }
    else {
        // coarse path: box rescan with guards
        #pragma unroll
        for (int i = 0; i < 8; i++) hist[lane*8+i] = 0;
        __syncwarp();
        int cnt = 0, ncov = 0;
        for (int yy = y0; yy <= y1; yy++) {
            int lo = cs[yy*GC + x0];
            int hi = cs[yy*GC + x1 + 1];
            for (int j = lo + lane; j < hi; j += 32) {
                float2 s = sl[j];
                float dx = t.x - s.x, dy = t.y - s.y;
                float d = fmaf(dy, dy, dx*dx);
                if (d < 0.04f) { cnt++; atomicAdd(&hist[min(255,(int)(d*6400.0f))], 1); }
                if (d < R1SQ) ncov++;
            }
        }
        #pragma unroll
        for (int o = 16; o; o >>= 1) {
            cnt  += __shfl_xor_sync(FULLM, cnt,  o);
            ncov += __shfl_xor_sync(FULLM, ncov, o);
        }
        if (ncov >= KK) mode = 1;
        else {
            mode = 2;
            #pragma unroll
            for (int i = 0; i < 8; i++) hist[lane*8+i] = 0;
            __syncwarp();
            cnt = 0;
            for (int j = lane; j < NN; j += 32) {
                float2 s = sl[j];
                float dx = t.x - s.x, dy = t.y - s.y;
                float d = fmaf(dy, dy, dx*dx);
                if (d < 0.04f) { cnt++; atomicAdd(&hist[min(255,(int)(d*6400.0f))], 1); }
            }
            #pragma unroll
            for (int o = 16; o; o >>= 1) cnt += __shfl_xor_sync(FULLM, cnt, o);
        }
        hsc = 6400.0f; hbound = 0.04f;

        if (cnt <= KK) {
            // emit everything in traversal order, pad with zeros
            int pos = 0;
            int yB = (mode == 2) ? 1 : (y1 - y0 + 1);
            for (int yi = 0; yi < yB; yi++) {
                int lo, hi;
                if (mode == 2) { lo = 0; hi = NN; }
                else { int yy = y0 + yi; lo = cs[yy*GC + x0]; hi = cs[yy*GC + x1 + 1]; }
                for (int base = lo; base < hi; base += 32) {
                    int j = base + lane;
                    float d = 1e9f;
                    if (j < hi) {
                        float2 s = sl[j];
                        float dx = t.x - s.x, dy = t.y - s.y;
                        d = fmaf(dy, dy, dx*dx);
                    }
                    bool hit = d < 0.04f;
                    unsigned bm = __ballot_sync(FULLM, hit);
                    int p = pos + __popc(bm & lmask);
                    if (hit && p < KK) { oid[p] = sid[j]; op[p] = __expf(-d*kInv); }
                    pos += __popc(bm);
                }
            }
            for (int p = pos + lane; p < KK; p += 32) { oid[p] = 0; op[p] = 0.0f; }
            return;
        }
    }
    __syncwarp();

    // ---- threshold bin via warp prefix over 256 bins ----
    int h[8]; int part = 0;
    #pragma unroll
    for (int i = 0; i < 8; i++) { h[i] = hist[lane*8+i]; part += h[i]; }
    int inc = part;
    #pragma unroll
    for (int off = 1; off < 32; off <<= 1) {
        int y = __shfl_up_sync(FULLM, inc, off);
        if (lane >= off) inc += y;
    }
    int exc = inc - part;
    int tb = -1, r = 0;
    if (exc < KK && KK <= inc) {
        int c = exc;
        #pragma unroll
        for (int i = 0; i < 8; i++) {
            if (tb < 0) {
                if (c + h[i] >= KK) { tb = lane*8 + i; r = KK - c; }
                else c += h[i];
            }
        }
    }
    int srcl = __ffs(__ballot_sync(FULLM, tb >= 0)) - 1;
    tb = __shfl_sync(FULLM, tb, srcl);
    r  = __shfl_sync(FULLM, r,  srcl);
    float dmax = (float)(tb + 1) / hsc;     // all selected/tied have d < dmax

    // ---- pass 2: pruned to dmax-circle; emit + collect ties ----
    int pos = 0, ntie = 0;
    int Y0 = (mode == 2) ? 0 : y0, Y1 = (mode == 2) ? GC-1 : y1;
    int X0 = (mode == 2) ? 0 : x0, X1 = (mode == 2) ? GC-1 : x1;
    for (int yy = Y0; yy <= Y1; yy++) {
        float ylo = yy*GCI;
        float dyv = fmaxf(0.0f, fmaxf(ylo - t.y, t.y - (ylo+GCI)));
        float bud = dmax - dyv*dyv;
        if (bud <= 0.0f) continue;
        float rx = sqrtf(bud);
        int xlo = max(X0, (int)((t.x - rx)*GC));
        int xhi = min(X1, (int)((t.x + rx)*GC));
        int lo = cs[yy*GC + xlo];
        int hi = cs[yy*GC + xhi + 1];
        for (int base = lo; base < hi; base += 32) {
            int j = base + lane;
            float d = 1e9f;
            if (j < hi) {
                float2 s = sl[j];
                float dx = t.x - s.x, dy = t.y - s.y;
                d = fmaf(dy, dy, dx*dx);
            }
            int bn = (d < hbound) ? min(255,(int)(d*hsc)) : 300;
            bool sel = bn < tb, tie = bn == tb;
            unsigned bs = __ballot_sync(FULLM, sel);
            int p = pos + __popc(bs & lmask);
            if (sel) { oid[p] = sid[j]; op[p] = __expf(-d*kInv); }
            pos += __popc(bs);
            unsigned bt = __ballot_sync(FULLM, tie);
            int q = ntie + __popc(bt & lmask);
            if (tie && q < TIE_CAP) { s_td[warp][q] = d; s_tj[warp][q] = (unsigned short)j; }
            ntie += __popc(bt);
        }
    }
    __syncwarp();
    if (lane == 0) {
        int nt = min(ntie, TIE_CAP);
        int rr = min(r, nt);
        for (int k2 = 0; k2 < rr; k2++) {
            float best = 1e30f; int bj = 0;
            for (int j2 = 0; j2 < nt; j2++)
                if (s_td[warp][j2] < best) { best = s_td[warp][j2]; bj = j2; }
            oid[pos+k2] = sid[s_tj[warp][bj]];
            op[pos+k2]  = __expf(-best*kInv);
            s_td[warp][bj] = 1e30f;
        }
        for (int k2 = rr; k2 < r; k2++) { oid[pos+k2] = 0; op[pos+k2] = 0.0f; }
    }
}

// ---------------------------------------------------------------------------
// persistent Sinkhorn (two-level reduction, no global atomics) + fp16 epilogue
// ---------------------------------------------------------------------------
__device__ __forceinline__ unsigned ld_acq(const unsigned* p) {
    unsigned v;
    asm volatile("ld.acquire.gpu.u32 %0, [%1];" : "=r"(v) : "l"(p) : "memory");
    return v;
}
__device__ __forceinline__ void st_rel(unsigned* p, unsigned v) {
    asm volatile("st.release.gpu.u32 [%0], %1;" :: "l"(p), "r"(v) : "memory");
}
__device__ __forceinline__ void gridbar() {
    __syncthreads();
    if (threadIdx.x == 0) {
        unsigned g = ld_acq(&g_bargen);
        __threadfence();
        if (atomicAdd(&g_barcnt, 1u) == NBLK - 1) {
            g_barcnt = 0;
            st_rel(&g_bargen, g + 1);
        } else {
            while (ld_acq(&g_bargen) == g) {}
        }
    }
    __syncthreads();
}

__global__ void __launch_bounds__(NTHR, 1) k_sink(float* __restrict__ out) {
    __shared__ float s_tab[NN];      // reciprocal ev table
    __shared__ float s_acc[NN];      // partial colsum accumulator / reduce scratch
    int lane = threadIdx.x & 31;
    int warp = threadIdx.x >> 5;        // 0..31
    int blk = blockIdx.x;               // 0..127  (32 blocks per batch)
    int b = blk >> 5;
    int bofs = b * NN;
    int rbase = blk*128 + warp*4;       // global row base (batch-aligned)
    int zcol = (blk & 31)*128;          // owned 128-column slice within batch

    int   i0[4], i1[4];
    float p0[4], p1[4], eu[4];

    #pragma unroll
    for (int k = 0; k < 4; k++) {
        int r = rbase + k;
        const int*   ri = &g_idx[(size_t)r*KK];
        const float* rp = &g_p[(size_t)r*KK];
        i0[k] = ri[lane];   i1[k] = ri[lane+32];
        p0[k] = rp[lane];   p1[k] = rp[lane+32];
    }

    #pragma unroll 1
    for (int t = 0; t < 8; t++) {
        if (t > 0) {
            #pragma unroll
            for (int x = 0; x < NN/NTHR; x++)
                s_tab[threadIdx.x + x*NTHR] = __ldcg(&g_ev[bofs + threadIdx.x + x*NTHR]);
        }
        #pragma unroll
        for (int x = 0; x < NN/NTHR; x++)
            s_acc[threadIdx.x + x*NTHR] = 0.0f;
        __syncthreads();

        #pragma unroll
        for (int k = 0; k < 4; k++) {
            float s;
            if (t == 0) s = p0[k] + p1[k];                 // ev == 1 initially
            else        s = p0[k]*s_tab[i0[k]] + p1[k]*s_tab[i1[k]];
            #pragma unroll
            for (int o = 16; o; o >>= 1) s += __shfl_xor_sync(FULLM, s, o);
            float e = (s > 0.0f) ? 1.0f/s : 0.0f;
            eu[k] = e;
            float w0 = p0[k]*e, w1 = p1[k]*e;
            if (w0 != 0.0f) atomicAdd(&s_acc[i0[k]], w0);
            if (w1 != 0.0f) atomicAdd(&s_acc[i1[k]], w1);
        }
        __syncthreads();

        #pragma unroll
        for (int x = 0; x < NN/NTHR; x++)
            g_part[(size_t)blk*NN + threadIdx.x + x*NTHR] = s_acc[threadIdx.x + x*NTHR];
        gridbar();

        {
            int p8 = threadIdx.x >> 7;     // 0..7
            int c  = threadIdx.x & 127;
            float s = 0.0f;
            #pragma unroll
            for (int q = 0; q < 4; q++)
                s += __ldcg(&g_part[(size_t)(b*32 + p8 + q*8)*NN + zcol + c]);
            s_acc[p8*128 + c] = s;
            __syncthreads();
            if (threadIdx.x < 128) {
                float tot = 0.0f;
                #pragma unroll
                for (int g2 = 0; g2 < 8; g2++) tot += s_acc[g2*128 + threadIdx.x];
                g_ev[bofs + zcol + threadIdx.x] = (tot > 0.0f) ? 1.0f/tot : 0.0f;
            }
        }
        gridbar();
    }

    // ---- epilogue: fp16 feature gathers ----
    #pragma unroll
    for (int x = 0; x < NN/NTHR; x++)
        s_tab[threadIdx.x + x*NTHR] = __ldcg(&g_ev[bofs + threadIdx.x + x*NTHR]);
    __syncthreads();
    const __half* fh = g_fh + (size_t)b*NN*DD;
    #pragma unroll 1
    for (int k = 0; k < 4; k++) {
        int r = rbase + k;
        float w0 = p0[k]*eu[k]*s_tab[i0[k]];
        float w1 = p1[k]*eu[k]*s_tab[i1[k]];
        float4 acc = make_float4(0.f, 0.f, 0.f, 0.f);
        #pragma unroll 16
        for (int j = 0; j < KK; j++) {
            int src = j & 31;
            float wj = __shfl_sync(FULLM, (j < 32) ? w0 : w1, src);
            int   ij = __shfl_sync(FULLM, (j < 32) ? i0[k] : i1[k], src);
            uint2 v = ((const uint2*)(fh + (size_t)ij*DD))[lane];
            __half2 h0 = *(__half2*)&v.x;
            __half2 h1 = *(__half2*)&v.y;
            float2 f0 = __half22float2(h0);
            float2 f1 = __half22float2(h1);
            acc.x = fmaf(wj, f0.x, acc.x);
            acc.y = fmaf(wj, f0.y, acc.y);
            acc.z = fmaf(wj, f1.x, acc.z);
            acc.w = fmaf(wj, f1.y, acc.w);
        }
        ((float4*)(out + (size_t)r*DD))[lane] = acc;
    }
}

extern "C" void kernel_launch(void* const* d_in, const int* in_sizes, int n_in,
                              void* d_out, int out_size) {
    const float*  feats = (const float*)d_in[0];
    const float2* slocs = (const float2*)d_in[1];
    const float2* tlocs = (const float2*)d_in[2];
    float* out = (float*)d_out;

    k_bin<<<BB, 1024>>>(slocs);
    k_half<<<(BB*NN*DD/4)/256, 256>>>(feats);
    k_topk<<<(BB*MM)/TK_WARPS, TK_WARPS*32>>>(tlocs);
    k_sink<<<NBLK, NTHR>>>(out);
}